// round 17
// baseline (speedup 1.0000x reference)
#include <cuda_runtime.h>
#include <cuda_bf16.h>
#include <cstdint>
#include <math.h>

// Problem constants (fixed by the reference: N=4096, D=256, H=8)
#define NN 4096
#define DD 256
#define HH 8
#define WPR 64   // 64-bit words per mask row: 4096/64

// ---------------- scratch (device globals; no allocation allowed) ----------
__device__ float g_Q[NN * DD];
__device__ float g_K[NN * DD];
__device__ float g_V[NN * DD];
__device__ float g_proj[NN * DD];
__device__ unsigned long long g_mask[NN * WPR];
// bf16 hi/lo splits for tensor-core GEMMs
__device__ __nv_bfloat16 g_xh[NN * DD], g_xl[NN * DD];
__device__ __nv_bfloat16 g_wh[4 * DD * DD], g_wl[4 * DD * DD];
__device__ __nv_bfloat16 g_ah[NN * DD], g_al[NN * DD];  // attn output split

// ---------------- mask kernels ---------------------------------------------
__global__ void zero_mask_kernel() {
    int t = blockIdx.x * blockDim.x + threadIdx.x;
    if (t < NN * WPR) g_mask[t] = 0ULL;
}

__global__ void build_mask_kernel(const int* __restrict__ ei, int E) {
    int t = blockIdx.x * blockDim.x + threadIdx.x;
    if (t < NN) {
        atomicOr(&g_mask[(size_t)t * WPR + (t >> 6)], 1ULL << (t & 63));
    }
    if (t < E) {
        int s = ei[t];        // src
        int d = ei[E + t];    // dst
        atomicOr(&g_mask[(size_t)d * WPR + (s >> 6)], 1ULL << (s & 63));
    }
}

// ---------------- fused fp32 -> bf16 hi/lo split (x + all 4 weights) -------
__global__ void split_all_kernel(const float* __restrict__ x,
                                 const float* __restrict__ Wq,
                                 const float* __restrict__ Wk,
                                 const float* __restrict__ Wv,
                                 const float* __restrict__ Wo) {
    const int total = NN * DD + 4 * DD * DD;
    int i = blockIdx.x * blockDim.x + threadIdx.x;
    if (i >= total) return;
    float v;
    __nv_bfloat16 *h, *l;
    int idx;
    if (i < NN * DD) {
        v = x[i]; h = g_xh; l = g_xl; idx = i;
    } else {
        int w = i - NN * DD;           // DD*DD == 65536
        int j = w >> 16;
        const float* src = (j == 0) ? Wq : (j == 1) ? Wk : (j == 2) ? Wv : Wo;
        v = src[w & 65535];
        h = g_wh; l = g_wl; idx = w;
    }
    __nv_bfloat16 hh = __float2bfloat16(v);
    h[idx] = hh;
    l[idx] = __float2bfloat16(v - __bfloat162float(hh));
}

// ---------------- bf16x3 mma.sync GEMM (small blocks, high occupancy) -------
// C[64x64 tile] = A @ W^T, A = Ah+Al, W = Wh+Wl (bf16 splits), f32 accum:
// D += Ah*Wh + Ah*Wl + Al*Wh  (lo*lo dropped, ~2^-16 rel err).
// 128 threads, 4 warps in 2x2, warp tile 32x32, k-tile 32, 2-stage cp.async.
// Static smem 40KB -> ~5 blocks/SM for latency hiding.
__device__ __forceinline__ void mma16816(float* d, const unsigned* a, const unsigned* b) {
    asm volatile(
        "mma.sync.aligned.m16n8k16.row.col.f32.bf16.bf16.f32 "
        "{%0,%1,%2,%3}, {%4,%5,%6,%7}, {%8,%9}, {%0,%1,%2,%3};"
        : "+f"(d[0]), "+f"(d[1]), "+f"(d[2]), "+f"(d[3])
        : "r"(a[0]), "r"(a[1]), "r"(a[2]), "r"(a[3]), "r"(b[0]), "r"(b[1]));
}
__device__ __forceinline__ void ldm_x4(unsigned* r, const void* p) {
    unsigned addr = (unsigned)__cvta_generic_to_shared(p);
    asm volatile("ldmatrix.sync.aligned.m8n8.x4.shared.b16 {%0,%1,%2,%3}, [%4];"
                 : "=r"(r[0]), "=r"(r[1]), "=r"(r[2]), "=r"(r[3]) : "r"(addr));
}
__device__ __forceinline__ void ldm_x2(unsigned* r, const void* p) {
    unsigned addr = (unsigned)__cvta_generic_to_shared(p);
    asm volatile("ldmatrix.sync.aligned.m8n8.x2.shared.b16 {%0,%1}, [%2];"
                 : "=r"(r[0]), "=r"(r[1]) : "r"(addr));
}
__device__ __forceinline__ void cpa16(const void* dst, const void* src) {
    unsigned d = (unsigned)__cvta_generic_to_shared(dst);
    asm volatile("cp.async.cg.shared.global [%0], [%1], 16;" :: "r"(d), "l"(src));
}

#define ASTR 40  // smem row stride in bf16 (32 + 8 pad) -> conflict-free ldmatrix

__device__ __forceinline__ void gemm_bf16_tile(const __nv_bfloat16* __restrict__ Agh,
                                               const __nv_bfloat16* __restrict__ Agl,
                                               const __nv_bfloat16* __restrict__ Wh,
                                               const __nv_bfloat16* __restrict__ Wl,
                                               float* __restrict__ C) {
    // [stage][matrix: Ah,Al,Bh,Bl][row][k]
    __shared__ __nv_bfloat16 S[2][4][64][ASTR];

    const int tid = threadIdx.x;
    const int lane = tid & 31;
    const int w = tid >> 5;
    const int wm = w >> 1;            // 0..1
    const int wn = w & 1;             // 0..1
    const int row0 = blockIdx.y * 64;
    const int col0 = blockIdx.x * 64;

    float d[2][4][4];
#pragma unroll
    for (int i = 0; i < 2; i++)
#pragma unroll
        for (int j = 0; j < 4; j++)
#pragma unroll
            for (int k = 0; k < 4; k++) d[i][j][k] = 0.0f;

    // stage loader: 8 cp.async per thread
    auto stage = [&](int st, int k0) {
#pragma unroll
        for (int i = 0; i < 2; i++) {
            int g = tid + i * 128;
            int r = g >> 2, q = (g & 3) * 8;
            const size_t ao = (size_t)(row0 + r) * 256 + k0 + q;
            const size_t bo = (size_t)(col0 + r) * 256 + k0 + q;
            cpa16(&S[st][0][r][q], Agh + ao);
            cpa16(&S[st][1][r][q], Agl + ao);
            cpa16(&S[st][2][r][q], Wh + bo);
            cpa16(&S[st][3][r][q], Wl + bo);
        }
        asm volatile("cp.async.commit_group;" ::: "memory");
    };

    stage(0, 0);

    int st = 0;
    for (int k0 = 0; k0 < 256; k0 += 32, st ^= 1) {
        if (k0 + 32 < 256) {
            stage(st ^ 1, k0 + 32);
            asm volatile("cp.async.wait_group 1;" ::: "memory");
        } else {
            asm volatile("cp.async.wait_group 0;" ::: "memory");
        }
        __syncthreads();

#pragma unroll
        for (int ks = 0; ks < 2; ks++) {
            unsigned ah[2][4], al[2][4], bh[4][2], bl[4][2];
#pragma unroll
            for (int mt = 0; mt < 2; mt++) {
                int ar = wm * 32 + mt * 16 + ((lane >> 3) & 1) * 8 + (lane & 7);
                int ac = ks * 16 + ((lane >> 4) & 1) * 8;
                ldm_x4(ah[mt], &S[st][0][ar][ac]);
                ldm_x4(al[mt], &S[st][1][ar][ac]);
            }
#pragma unroll
            for (int nt = 0; nt < 4; nt++) {
                int br = wn * 32 + nt * 8 + (lane & 7);
                int bc = ks * 16 + ((lane >> 3) & 1) * 8;
                ldm_x2(bh[nt], &S[st][2][br][bc]);
                ldm_x2(bl[nt], &S[st][3][br][bc]);
            }
#pragma unroll
            for (int mt = 0; mt < 2; mt++)
#pragma unroll
                for (int nt = 0; nt < 4; nt++) {
                    mma16816(d[mt][nt], ah[mt], bh[nt]);
                    mma16816(d[mt][nt], ah[mt], bl[nt]);
                    mma16816(d[mt][nt], al[mt], bh[nt]);
                }
        }
        __syncthreads();
    }

    const int gid = lane >> 2, tig = lane & 3;
#pragma unroll
    for (int mt = 0; mt < 2; mt++)
#pragma unroll
        for (int nt = 0; nt < 4; nt++) {
            int r = row0 + wm * 32 + mt * 16 + gid;
            int c = col0 + wn * 32 + nt * 8 + tig * 2;
            *(float2*)(C + (size_t)r * 256 + c) = make_float2(d[mt][nt][0], d[mt][nt][1]);
            *(float2*)(C + (size_t)(r + 8) * 256 + c) = make_float2(d[mt][nt][2], d[mt][nt][3]);
        }
}

__global__ void __launch_bounds__(128) gemm_qkv_kernel() {
    const int z = blockIdx.z;  // 0=Q,1=K,2=V
    float* C = (z == 0) ? g_Q : (z == 1) ? g_K : g_V;
    gemm_bf16_tile(g_xh, g_xl, g_wh + (size_t)z * DD * DD, g_wl + (size_t)z * DD * DD, C);
}

__global__ void __launch_bounds__(128) gemm_out_kernel() {
    gemm_bf16_tile(g_ah, g_al, g_wh + (size_t)3 * DD * DD, g_wl + (size_t)3 * DD * DD,
                   g_proj);
}

// ---------------- sparse masked attention (warp-per-node, 4-way batched) ----
// One warp = one node; lane l owns dims 8l..8l+7 (head h = lanes 4h..4h+3).
// The bitmask iterator is warp-uniform (ballot + broadcast word); each step
// gathers up to 4 neighbor indices, issues all 16 LDG.128 together (MLP~16),
// then computes 4 dots + exps + fmas. No running max (scores bounded; exp in
// fp32 is safe — validated rel_err 2.4e-6 in R8).
__global__ void __launch_bounds__(256) attn_kernel() {
    const int warp = threadIdx.x >> 5;
    const int lane = threadIdx.x & 31;
    const int n = blockIdx.x * 8 + warp;

    const float* qrow = g_Q + (size_t)n * DD + lane * 8;
    const float4 q0 = *(const float4*)qrow;
    const float4 q1 = *(const float4*)(qrow + 4);

    const unsigned long long wA = g_mask[(size_t)n * WPR + lane];
    const unsigned long long wB = g_mask[(size_t)n * WPR + 32 + lane];

    float S = 0.0f;
    float a0 = 0, a1 = 0, a2 = 0, a3 = 0, a4 = 0, a5 = 0, a6 = 0, a7 = 0;
    const float inv_scale = 0.17677669529663688f;  // 1/sqrt(32)

    // warp-uniform bit iterator state
    int half = 0;
    unsigned nz = __ballot_sync(0xffffffffu, wA != 0ULL);
    unsigned long long word = 0ULL;
    int jbase = 0;

    for (;;) {
        // ---- gather up to 4 neighbor indices (uniform across the warp) ----
        int js[4];
        int c = 0;
        while (c < 4) {
            if (word) {
                const int b = __ffsll((long long)word) - 1;
                word &= word - 1;
                js[c++] = jbase + b;
            } else if (nz) {
                const int sl = __ffs(nz) - 1;
                nz &= nz - 1;
                word = __shfl_sync(0xffffffffu, half ? wB : wA, sl);
                jbase = (half * 32 + sl) << 6;
            } else if (half == 0) {
                half = 1;
                nz = __ballot_sync(0xffffffffu, wB != 0ULL);
            } else {
                break;
            }
        }
        if (c == 0) break;

        // ---- batched loads: all K/V rows issued together ----
        float4 k0[4], k1[4], v0[4], v1[4];
#pragma unroll
        for (int t = 0; t < 4; t++) {
            if (t < c) {
                const float* kr = g_K + (size_t)js[t] * DD + lane * 8;
                k0[t] = *(const float4*)kr;
                k1[t] = *(const float4*)(kr + 4);
                const float* vr = g_V + (size_t)js[t] * DD + lane * 8;
                v0[t] = *(const float4*)vr;
                v1[t] = *(const float4*)(vr + 4);
            }
        }

        // ---- dots (independent chains), group-of-4 reduce, exp, accum ----
        float dot[4];
#pragma unroll
        for (int t = 0; t < 4; t++) {
            if (t < c) {
                float dd = q0.x * k0[t].x;
                dd = fmaf(q0.y, k0[t].y, dd);
                dd = fmaf(q0.z, k0[t].z, dd);
                dd = fmaf(q0.w, k0[t].w, dd);
                dd = fmaf(q1.x, k1[t].x, dd);
                dd = fmaf(q1.y, k1[t].y, dd);
                dd = fmaf(q1.z, k1[t].z, dd);
                dd = fmaf(q1.w, k1[t].w, dd);
                dot[t] = dd;
            }
        }
#pragma unroll
        for (int t = 0; t < 4; t++)
            if (t < c) dot[t] += __shfl_xor_sync(0xffffffffu, dot[t], 1);
#pragma unroll
        for (int t = 0; t < 4; t++)
            if (t < c) dot[t] += __shfl_xor_sync(0xffffffffu, dot[t], 2);

        float e[4];
#pragma unroll
        for (int t = 0; t < 4; t++)
            e[t] = (t < c) ? __expf(dot[t] * inv_scale) : 0.0f;
        S += (e[0] + e[1]) + (e[2] + e[3]);
#pragma unroll
        for (int t = 0; t < 4; t++) {
            if (t < c) {
                a0 = fmaf(e[t], v0[t].x, a0);
                a1 = fmaf(e[t], v0[t].y, a1);
                a2 = fmaf(e[t], v0[t].z, a2);
                a3 = fmaf(e[t], v0[t].w, a3);
                a4 = fmaf(e[t], v1[t].x, a4);
                a5 = fmaf(e[t], v1[t].y, a5);
                a6 = fmaf(e[t], v1[t].z, a6);
                a7 = fmaf(e[t], v1[t].w, a7);
            }
        }
        if (c < 4) break;  // iterator exhausted
    }

    const float inv = 1.0f / S;
    float o[8] = {a0 * inv, a1 * inv, a2 * inv, a3 * inv,
                  a4 * inv, a5 * inv, a6 * inv, a7 * inv};
    __nv_bfloat16 hb[8], lb[8];
#pragma unroll
    for (int dd = 0; dd < 8; dd++) {
        hb[dd] = __float2bfloat16(o[dd]);
        lb[dd] = __float2bfloat16(o[dd] - __bfloat162float(hb[dd]));
    }
    const size_t oi = (size_t)n * DD + lane * 8;
    *(uint4*)&g_ah[oi] = *(uint4*)hb;
    *(uint4*)&g_al[oi] = *(uint4*)lb;
}

// ---------------- residual + bias + LayerNorm (warp-shuffle) ----------------
__global__ void __launch_bounds__(256) ln_kernel(const float* __restrict__ x,
                                                 const float* __restrict__ bo,
                                                 const float* __restrict__ gamma,
                                                 const float* __restrict__ beta,
                                                 float* __restrict__ out) {
    const int n = blockIdx.x;
    const int t = threadIdx.x;
    const int lane = t & 31;
    const int w = t >> 5;
    __shared__ float s1[8], s2[8];

    const float hv = x[(size_t)n * DD + t] + g_proj[(size_t)n * DD + t] + bo[t];

    float r1 = hv, r2 = hv * hv;
#pragma unroll
    for (int o = 16; o > 0; o >>= 1) {
        r1 += __shfl_xor_sync(0xffffffffu, r1, o);
        r2 += __shfl_xor_sync(0xffffffffu, r2, o);
    }
    if (lane == 0) { s1[w] = r1; s2[w] = r2; }
    __syncthreads();
    float t1 = 0, t2 = 0;
#pragma unroll
    for (int i = 0; i < 8; i++) { t1 += s1[i]; t2 += s2[i]; }
    const float mu = t1 * (1.0f / DD);
    const float var = t2 * (1.0f / DD) - mu * mu;
    const float rstd = rsqrtf(var + 1e-5f);
    out[(size_t)n * DD + t] = (hv - mu) * rstd * gamma[t] + beta[t];
}

// ---------------- launcher --------------------------------------------------
extern "C" void kernel_launch(void* const* d_in, const int* in_sizes, int n_in,
                              void* d_out, int out_size) {
    const float* x     = (const float*)d_in[0];
    const int*   ei    = (const int*)d_in[1];
    const float* Wq    = (const float*)d_in[2];
    const float* Wk    = (const float*)d_in[3];
    const float* Wv    = (const float*)d_in[4];
    const float* Wo    = (const float*)d_in[5];
    const float* bo    = (const float*)d_in[6];
    const float* gamma = (const float*)d_in[7];
    const float* beta  = (const float*)d_in[8];
    const int E = in_sizes[1] / 2;

    zero_mask_kernel<<<(NN * WPR + 511) / 512, 512>>>();
    {
        int work = (E > NN) ? E : NN;
        build_mask_kernel<<<(work + 255) / 256, 256>>>(ei, E);
    }
    {
        const int total = NN * DD + 4 * DD * DD;
        split_all_kernel<<<(total + 255) / 256, 256>>>(x, Wq, Wk, Wv, Wo);
    }

    gemm_qkv_kernel<<<dim3(4, 64, 3), 128>>>();
    attn_kernel<<<NN / 8, 256>>>();
    gemm_out_kernel<<<dim3(4, 64, 1), 128>>>();
    ln_kernel<<<NN, 256>>>(x, bo, gamma, beta, (float*)d_out);
}